// round 11
// baseline (speedup 1.0000x reference)
#include <cuda_runtime.h>
#include <math.h>
#include <stdint.h>

#define TOPK   64
#define NANCH  340
#define MS     28
#define NROI   128          // B(2) * TOPK(64)

typedef unsigned long long ull;

// ---------------- device scratch (no allocation allowed) ----------------
__device__ float g_box [NROI][4];
__device__ int   g_bint[NROI][4];
__device__ int   g_keep[NROI];
__device__ int   g_list[NROI];     // compacted kept roi ids
__device__ int   g_nitems;         // 7 * nkept
__device__ float g_logit[NROI][MS*MS];
__device__ float g_roi[NROI][256][900];       // padded 30x30 per channel
__device__ float g_w1t[256*9*128];            // [(ci*9+tap)*128 + oc]

// out layout (fp32): scores[128] | boxes[512] | labels[128] | masks[2*64*512*512] | keep[128]
#define OFF_SCORES 0
#define OFF_BOXES  128
#define OFF_LABELS 640
#define OFF_MASKS  768
#define OFF_KEEP   33555200

// ---------------- packed fp32x2 helpers (Blackwell FFMA2) ----------------
__device__ __forceinline__ ull pack2(float x) {
    ull r; asm("mov.b64 %0, {%1, %1};" : "=l"(r) : "f"(x)); return r;
}
__device__ __forceinline__ void fma2(ull& d, ull a, ull b) {
    asm("fma.rn.f32x2 %0, %1, %2, %0;" : "+l"(d) : "l"(a), "l"(b));
}
__device__ __forceinline__ float2 unpack2(ull v) {
    float2 f; asm("mov.b64 {%0, %1}, %2;" : "=f"(f.x), "=f"(f.y) : "l"(v)); return f;
}
__device__ __forceinline__ uint32_t s2u(const void* p) {
    return (uint32_t)__cvta_generic_to_shared(p);
}
__device__ __forceinline__ void cpasync16(uint32_t smem, const void* g) {
    asm volatile("cp.async.ca.shared.global [%0], [%1], 16;" :: "r"(smem), "l"(g));
}
#define CP_COMMIT()  asm volatile("cp.async.commit_group;" ::: "memory")
#define CP_WAIT1()   asm volatile("cp.async.wait_group 1;" ::: "memory")
#define CP_WAIT0()   asm volatile("cp.async.wait_group 0;" ::: "memory")

// =======================================================================
// K0: transpose conv1 weights -> g_w1t[(ci*9+tap)*128 + oc]
// =======================================================================
__global__ void k0_wt(const float* __restrict__ w1)
{
    int idx = blockIdx.x * 256 + threadIdx.x;
    if (idx < 256*9*128) {
        int oc = idx & 127;
        int ct = idx >> 7;          // ci*9+tap
        int ci = ct / 9, tap = ct - ci*9;
        g_w1t[idx] = w1[(size_t)oc*2304 + ci*9 + tap];
    }
}

// =======================================================================
// K1: decode + warp-shuffle top-k + NMS + outputs + compaction (1 block)
// =======================================================================
__global__ void k1_detect(const float* __restrict__ pred0,
                          const float* __restrict__ pred1,
                          const float* __restrict__ pred2,
                          const float* __restrict__ pred3,
                          float* __restrict__ out)
{
    int tid  = threadIdx.x;           // 384
    int wid  = tid >> 5, lane = tid & 31;

    __shared__ float sbox[2][NANCH][4];
    __shared__ ull   skey[2][NANCH];
    __shared__ int   topidx[2][TOPK];
    __shared__ float topsc [2][TOPK];
    __shared__ float kbox[2][TOPK][4];
    __shared__ int   keepf[2][TOPK];
    __shared__ int   woff[4];

    const float* preds[4] = {pred0, pred1, pred2, pred3};

    for (int a = tid; a < 2*NANCH; a += 384) {
        int b = a / NANCH, i = a - b*NANCH;
        int li, lv, H, stride;
        if      (i < 256) { li = i;       lv = 0; H = 16; stride = 32;  }
        else if (i < 320) { li = i - 256; lv = 1; H = 8;  stride = 64;  }
        else if (i < 336) { li = i - 320; lv = 2; H = 4;  stride = 128; }
        else              { li = i - 336; lv = 3; H = 2;  stride = 256; }
        int hw = H * H;
        const float* base = preds[lv] + b * 6 * hw;
        float v0 = base[li];
        float v1 = base[hw   + li];
        float v2 = base[2*hw + li];
        float v3 = base[3*hw + li];
        float v4 = base[4*hw + li];
        int y = li / H, x = li % H;
        float cx = (v0 + (float)x) * (float)stride;
        float cy = (v1 + (float)y) * (float)stride;
        float w  = expf(v2) * (float)stride;
        float h  = expf(v3) * (float)stride;
        sbox[b][i][0] = cx - w * 0.5f;
        sbox[b][i][1] = cy - h * 0.5f;
        sbox[b][i][2] = cx + w * 0.5f;
        sbox[b][i][3] = cy + h * 0.5f;
        float sc   = 1.f / (1.f + expf(-v4));
        float sval = (sc > 0.5f) ? sc : 0.f;
        skey[b][i] = ((ull)__float_as_uint(sval) << 32)
                   | (ull)(0xFFFFFFFFu - (unsigned)i);
    }
    __syncthreads();

    // warp 0 -> batch 0, warp 1 -> batch 1: 64 rounds, shfl reductions
    if (wid < 2) {
        int b = wid;
        for (int k = 0; k < TOPK; k++) {
            ull m = 0ULL;
            for (int i = lane; i < NANCH; i += 32) {
                ull v = skey[b][i]; if (v > m) m = v;
            }
            #pragma unroll
            for (int o = 16; o > 0; o >>= 1) {
                ull v = __shfl_down_sync(0xFFFFFFFFu, m, o);
                if (v > m) m = v;
            }
            m = __shfl_sync(0xFFFFFFFFu, m, 0);
            if (lane == 0) {
                int idx = (int)(0xFFFFFFFFu - (unsigned)(m & 0xFFFFFFFFu));
                topidx[b][k] = idx;
                topsc [b][k] = __uint_as_float((unsigned)(m >> 32));
                skey[b][idx] = 0ULL;
            }
            __syncwarp();
        }
    }
    __syncthreads();

    if (tid < 128) {
        int b = tid >> 6, j = tid & 63;
        int idx = topidx[b][j];
        for (int q = 0; q < 4; q++) kbox[b][j][q] = sbox[b][idx][q];
        keepf[b][j] = (topsc[b][j] > 0.5f) ? 1 : 0;
    }
    __syncthreads();

    for (int i = 0; i < TOPK; i++) {
        if (tid < 128) {
            int b = tid >> 6, j = tid & 63;
            if (j > i && keepf[b][j] && keepf[b][i]) {
                float ax0=kbox[b][i][0], ay0=kbox[b][i][1], ax1=kbox[b][i][2], ay1=kbox[b][i][3];
                float bx0=kbox[b][j][0], by0=kbox[b][j][1], bx1=kbox[b][j][2], by1=kbox[b][j][3];
                float aa = fmaxf(ax1-ax0,0.f)*fmaxf(ay1-ay0,0.f);
                float ab = fmaxf(bx1-bx0,0.f)*fmaxf(by1-by0,0.f);
                float ix0 = fmaxf(ax0,bx0), iy0 = fmaxf(ay0,by0);
                float ix1 = fminf(ax1,bx1), iy1 = fminf(ay1,by1);
                float inter = fmaxf(ix1-ix0,0.f)*fmaxf(iy1-iy0,0.f);
                float uni = aa + ab - inter;
                float iou = inter / fmaxf(uni, 1e-9f);
                if (iou > 0.5f) keepf[b][j] = 0;
            }
        }
        __syncthreads();
    }

    if (tid < 128) {
        int b = tid >> 6, j = tid & 63;
        int r = tid;
        int kp = keepf[b][j];
        out[OFF_SCORES + r] = kp ? topsc[b][j] : 0.f;
        for (int q = 0; q < 4; q++) out[OFF_BOXES + r*4 + q] = kbox[b][j][q];
        out[OFF_LABELS + r] = 0.f;
        out[OFF_KEEP   + r] = kp ? 1.f : 0.f;
        g_keep[r] = kp;
        for (int q = 0; q < 4; q++) {
            g_box[r][q] = kbox[b][j][q];
            float c = fminf(fmaxf(kbox[b][j][q], 0.f), 511.f);
            g_bint[r][q] = (int)c;
        }
    }
    __syncthreads();

    // compaction of kept rois (tids 0..127 = warps 0..3)
    if (tid < 128) {
        int kp = keepf[tid>>6][tid&63];
        unsigned ball = __ballot_sync(0xFFFFFFFFu, kp);
        if (lane == 0) woff[wid] = __popc(ball);
    }
    __syncthreads();
    if (tid == 0) {
        int s = 0;
        for (int w = 0; w < 4; w++) { int t = woff[w]; woff[w] = s; s += t; }
        g_nitems = 7 * s;
    }
    __syncthreads();
    if (tid < 128) {
        int kp = keepf[tid>>6][tid&63];
        unsigned ball = __ballot_sync(0xFFFFFFFFu, kp);
        int pre = __popc(ball & ((1u << lane) - 1u));
        if (kp) g_list[woff[wid] + pre] = tid;
    }
}

// =======================================================================
// K2: ROI-align into padded scratch
// =======================================================================
__global__ void k2_sample(const float* __restrict__ f0,
                          const float* __restrict__ f1,
                          const float* __restrict__ f2,
                          const float* __restrict__ f3)
{
    int r = blockIdx.y;
    if (!g_keep[r]) return;
    int b = r >> 6;
    float bx0 = g_box[r][0]*0.25f, by0 = g_box[r][1]*0.25f;
    float bx1 = g_box[r][2]*0.25f, by1 = g_box[r][3]*0.25f;
    float bw = (bx1 - bx0) / 28.f;
    float bh = (by1 - by0) / 28.f;
    const float* feats[4] = {f0, f1, f2, f3};
    int cbase = blockIdx.x * 32;

    for (int e = threadIdx.x; e < 32*900; e += blockDim.x) {
        int cl = e / 900; int pe = e - cl*900;
        int py = pe / 30; int px = pe - py*30;
        int c  = cbase + cl;
        float val = 0.f;
        if (py >= 1 && py <= 28 && px >= 1 && px <= 28) {
            int gx = px - 1, gy = py - 1;
            float xx = bx0 + ((float)gx + 0.5f) * bw;
            float yy = by0 + ((float)gy + 0.5f) * bh;
            xx = fminf(fmaxf(xx, 0.f), 127.f);
            yy = fminf(fmaxf(yy, 0.f), 127.f);
            int x0 = (int)floorf(xx), y0 = (int)floorf(yy);
            int x1 = min(x0 + 1, 127), y1 = min(y0 + 1, 127);
            float fx = xx - (float)x0, fy = yy - (float)y0;
            int l = c >> 6, cc = c & 63, dim = 128 >> l;
            const float* fp = feats[l] + (size_t)(b*64 + cc) * dim * dim;
            float v00 = fp[(y0>>l)*dim + (x0>>l)];
            float v01 = fp[(y0>>l)*dim + (x1>>l)];
            float v10 = fp[(y1>>l)*dim + (x0>>l)];
            float v11 = fp[(y1>>l)*dim + (x1>>l)];
            val = v00*(1.f-fy)*(1.f-fx) + v01*(1.f-fy)*fx
                + v10*fy*(1.f-fx)       + v11*fy*fx;
        }
        g_roi[r][c][pe] = val;
    }
}

// =======================================================================
// K3: conv1(3x3,256->128)+SiLU fused with conv2(1x1,128->1) -> logits.
// Retiled: 224 threads = 8 ty (16 oc each) x 28 tx (4 px each).
// Per tap: 4 pixel LDS.32 + 4 packs + 4 LDS.128 + 32 FFMA2 (72.7% fma
// issue share vs 63.6% before). 4-ci stages -> 64 iters, half the
// barriers. cp.async double-buffered weights.
// Accumulation order per (oc,px): ci ascending, ky, kx -> conv1
// accumulators bit-identical to R9.
// =======================================================================
__global__ void __launch_bounds__(224, 2)
k3_conv(const float* __restrict__ b1, const float* __restrict__ w2,
        const float* __restrict__ b2)
{
    int item = blockIdx.x;
    if (item >= g_nitems) return;
    int kidx = item / 7, rt = item - kidx*7;
    int r = g_list[kidx];

    int tid = threadIdx.x;            // 0..223
    int tx = tid % 28, ty = tid / 28; // tx: col, ty: oc group (16 oc)

    __shared__ __align__(16) float w_s[2][4608];   // [buf][(c*9+tap)*128+oc]
    __shared__ __align__(16) float in_s[2][4][180];// [buf][c][row*30+col]
    __shared__ float redbuf[8][112];

    // input prefetch: 720 elems/stage; slots e = tid + 224*j, j=0..3
    int en = (tid < 48) ? 4 : 3;      // 224*3=672, +48 = 720
    int ec[4], er[4];
    #pragma unroll
    for (int j = 0; j < 4; j++) {
        int e = tid + 224*j;
        if (e < 720) { ec[j] = e / 180; er[j] = e - ec[j]*180; }
        else         { ec[j] = 0;       er[j] = 0; }
    }
    const float* roi_base = &g_roi[r][0][0];
    int rowoff = rt * 120;            // (rt*4)*30

    uint32_t wdst[2] = { s2u(&w_s[0][0]), s2u(&w_s[1][0]) };
    float pin[4];

    // per-stage weight block: 4 ci * 9 taps * 128 oc = 4608 floats
    #define PREFETCH(s)                                                       \
    {                                                                         \
        const float* wsrc = g_w1t + (size_t)(s)*4608;                         \
        uint32_t wd = wdst[(s) & 1];                                          \
        for (int i = tid; i < 1152; i += 224)                                 \
            cpasync16(wd + i*16, wsrc + i*4);                                 \
        CP_COMMIT();                                                          \
        _Pragma("unroll")                                                     \
        for (int j = 0; j < 4; j++)                                           \
            if (j < en)                                                       \
                pin[j] = roi_base[(size_t)(4*(s) + ec[j])*900 + rowoff + er[j]];\
    }
    #define COMMITIN(s)                                                       \
    {                                                                         \
        _Pragma("unroll")                                                     \
        for (int j = 0; j < 4; j++)                                           \
            if (j < en)                                                       \
                in_s[(s)&1][ec[j]][er[j]] = pin[j];                           \
    }

    ull acc[8][4];                    // 8 oc-pairs x 4 px (rows)
    ull z = pack2(0.f);
    #pragma unroll
    for (int j = 0; j < 8; j++)
        #pragma unroll
        for (int p = 0; p < 4; p++) acc[j][p] = z;

    int oc0 = ty * 16;

    // prologue
    PREFETCH(0);
    COMMITIN(0);

    for (int it = 0; it < 64; it++) {
        int cur = it & 1;
        if (it + 1 < 64) { PREFETCH(it + 1); CP_WAIT1(); }
        else             { CP_WAIT0(); }
        __syncthreads();                      // w_s[cur] + in_s[cur] visible

        const float* wbuf = &w_s[cur][0];
        #pragma unroll
        for (int c = 0; c < 4; c++) {
            #pragma unroll
            for (int ky = 0; ky < 3; ky++) {
                #pragma unroll
                for (int kx = 0; kx < 3; kx++) {
                    const ulonglong2* wp =
                        (const ulonglong2*)(wbuf + (c*9 + ky*3 + kx)*128 + oc0);
                    ulonglong2 wq0 = wp[0], wq1 = wp[1];   // oc pairs 0..3
                    ulonglong2 wq2 = wp[2], wq3 = wp[3];   // oc pairs 4..7
                    const float* ib = &in_s[cur][c][ky*30 + kx + tx];
                    #pragma unroll
                    for (int p = 0; p < 4; p++) {
                        ull bb = pack2(ib[p*30]);
                        fma2(acc[0][p], wq0.x, bb);
                        fma2(acc[1][p], wq0.y, bb);
                        fma2(acc[2][p], wq1.x, bb);
                        fma2(acc[3][p], wq1.y, bb);
                        fma2(acc[4][p], wq2.x, bb);
                        fma2(acc[5][p], wq2.y, bb);
                        fma2(acc[6][p], wq3.x, bb);
                        fma2(acc[7][p], wq3.y, bb);
                    }
                }
            }
        }
        __syncthreads();                      // done reading cur buffers
        if (it + 1 < 64) COMMITIN(it + 1);    // fill in_s[(it+1)&1]
    }
    #undef PREFETCH
    #undef COMMITIN

    // SiLU + 1x1 conv partials (oc ascending within thread)
    float lp[4];
    #pragma unroll
    for (int p = 0; p < 4; p++) lp[p] = 0.f;
    #pragma unroll
    for (int j = 0; j < 8; j++) {
        int oca = oc0 + 2*j, ocb = oc0 + 2*j + 1;
        float ba = b1[oca], bb_ = b1[ocb];
        float wa = w2[oca], wb = w2[ocb];
        #pragma unroll
        for (int p = 0; p < 4; p++) {
            float2 v = unpack2(acc[j][p]);
            float ha = v.x + ba;
            float hb = v.y + bb_;
            lp[p] += wa * (ha / (1.f + expf(-ha)));
            lp[p] += wb * (hb / (1.f + expf(-hb)));
        }
    }
    #pragma unroll
    for (int p = 0; p < 4; p++) redbuf[ty][p*28 + tx] = lp[p];
    __syncthreads();
    if (tid < 112) {
        float s = b2[0];
        #pragma unroll
        for (int t = 0; t < 8; t++) s += redbuf[t][tid];
        int row = rt*4 + tid / 28, col = tid % 28;
        g_logit[r][row*28 + col] = s;   // sign(logit) == (sigmoid > 0.5)
    }
}

// =======================================================================
// K4: paste -> binary masks (float 0/1). grid (512 rows, 128 rois), 128 thr
// =======================================================================
__global__ void k4_paste(float* __restrict__ out)
{
    int r = blockIdx.y;
    int y = blockIdx.x;
    int tid = threadIdx.x;
    float4* dst = (float4*)(out + OFF_MASKS + (size_t)r*262144 + (size_t)y*512);

    __shared__ float brow[28];
    float4 v = make_float4(0.f, 0.f, 0.f, 0.f);
    int kp = g_keep[r];
    if (kp) {
        int x0 = g_bint[r][0], y0 = g_bint[r][1];
        int x1 = g_bint[r][2], y1 = g_bint[r][3];
        if (y >= y0 && y <= y1) {
            int h = y1 - y0 + 1, w = x1 - x0 + 1;
            int iy = min((y - y0) * 28 / h, 27);
            if (tid < 28) brow[tid] = (g_logit[r][iy*28 + tid] > 0.f) ? 1.f : 0.f;
            __syncthreads();
            float* vv = (float*)&v;
            #pragma unroll
            for (int q = 0; q < 4; q++) {
                int x = tid * 4 + q;
                if (x >= x0 && x <= x1) {
                    int ix = min((x - x0) * 28 / w, 27);
                    vv[q] = brow[ix];
                }
            }
        }
    }
    dst[tid] = v;
}

// =======================================================================
extern "C" void kernel_launch(void* const* d_in, const int* in_sizes, int n_in,
                              void* d_out, int out_size)
{
    const float* pred0 = (const float*)d_in[0];
    const float* pred1 = (const float*)d_in[1];
    const float* pred2 = (const float*)d_in[2];
    const float* pred3 = (const float*)d_in[3];
    const float* feat0 = (const float*)d_in[4];
    const float* feat1 = (const float*)d_in[5];
    const float* feat2 = (const float*)d_in[6];
    const float* feat3 = (const float*)d_in[7];
    const float* w1    = (const float*)d_in[8];
    const float* b1    = (const float*)d_in[9];
    const float* w2    = (const float*)d_in[10];
    const float* b2    = (const float*)d_in[11];
    float* out = (float*)d_out;
    (void)in_sizes; (void)n_in; (void)out_size;

    k0_wt    <<<1152, 256>>>(w1);
    k1_detect<<<1, 384>>>(pred0, pred1, pred2, pred3, out);
    k2_sample<<<dim3(8, NROI), 256>>>(feat0, feat1, feat2, feat3);
    k3_conv  <<<7 * NROI, 224>>>(b1, w2, b2);
    k4_paste <<<dim3(512, NROI), 128>>>(out);
}

// round 12
// speedup vs baseline: 1.0239x; 1.0239x over previous
#include <cuda_runtime.h>
#include <math.h>
#include <stdint.h>

#define TOPK   64
#define NANCH  340
#define MS     28
#define NROI   128          // B(2) * TOPK(64)

typedef unsigned long long ull;

// ---------------- device scratch (no allocation allowed) ----------------
__device__ float g_box [NROI][4];
__device__ int   g_bint[NROI][4];
__device__ int   g_keep[NROI];
__device__ int   g_list[NROI];     // compacted kept roi ids
__device__ int   g_nitems;         // 7 * nkept
__device__ float g_logit[NROI][MS*MS];
__device__ float g_roi[NROI][256][900];       // padded 30x30 per channel
__device__ float g_w1t[256*9*128];            // [(ci*9+tap)*128 + oc]
// channel-last transposed features: [b][y][x][c], c fastest (64 per level)
__device__ __align__(16) float g_ft0[2*128*128*64];
__device__ __align__(16) float g_ft1[2* 64* 64*64];
__device__ __align__(16) float g_ft2[2* 32* 32*64];
__device__ __align__(16) float g_ft3[2* 16* 16*64];

// out layout (fp32): scores[128] | boxes[512] | labels[128] | masks[2*64*512*512] | keep[128]
#define OFF_SCORES 0
#define OFF_BOXES  128
#define OFF_LABELS 640
#define OFF_MASKS  768
#define OFF_KEEP   33555200

// ---------------- packed fp32x2 helpers (Blackwell FFMA2) ----------------
__device__ __forceinline__ ull pack2(float x) {
    ull r; asm("mov.b64 %0, {%1, %1};" : "=l"(r) : "f"(x)); return r;
}
__device__ __forceinline__ void fma2(ull& d, ull a, ull b) {
    asm("fma.rn.f32x2 %0, %1, %2, %0;" : "+l"(d) : "l"(a), "l"(b));
}
__device__ __forceinline__ float2 unpack2(ull v) {
    float2 f; asm("mov.b64 {%0, %1}, %2;" : "=f"(f.x), "=f"(f.y) : "l"(v)); return f;
}
__device__ __forceinline__ uint32_t s2u(const void* p) {
    return (uint32_t)__cvta_generic_to_shared(p);
}
__device__ __forceinline__ void cpasync16(uint32_t smem, const void* g) {
    asm volatile("cp.async.ca.shared.global [%0], [%1], 16;" :: "r"(smem), "l"(g));
}
#define CP_COMMIT()  asm volatile("cp.async.commit_group;" ::: "memory")
#define CP_WAIT0()   asm volatile("cp.async.wait_group 0;" ::: "memory")

// =======================================================================
// K0a: transpose conv1 weights -> g_w1t[(ci*9+tap)*128 + oc]
// =======================================================================
__global__ void k0_wt(const float* __restrict__ w1)
{
    int idx = blockIdx.x * 256 + threadIdx.x;
    if (idx < 256*9*128) {
        int oc = idx & 127;
        int ct = idx >> 7;          // ci*9+tap
        int ci = ct / 9, tap = ct - ci*9;
        g_w1t[idx] = w1[(size_t)oc*2304 + ci*9 + tap];
    }
}

// =======================================================================
// K0b: transpose features [b][c][y][x] -> [b][y][x][c] (c fastest)
// =======================================================================
__global__ void k0_ft(const float* __restrict__ src, float* __restrict__ dst,
                      int dim)
{
    int idx = blockIdx.x * 256 + threadIdx.x;
    int total = 2 * 64 * dim * dim;
    if (idx >= total) return;
    int x = idx % dim; int t = idx / dim;
    int y = t % dim;   t /= dim;
    int c = t % 64;    int b = t / 64;
    dst[(size_t)(((b*dim) + y)*dim + x)*64 + c] = src[idx];
}

// =======================================================================
// K1: decode + warp-shuffle top-k + NMS + outputs + compaction (1 block)
// =======================================================================
__global__ void k1_detect(const float* __restrict__ pred0,
                          const float* __restrict__ pred1,
                          const float* __restrict__ pred2,
                          const float* __restrict__ pred3,
                          float* __restrict__ out)
{
    int tid  = threadIdx.x;           // 384
    int wid  = tid >> 5, lane = tid & 31;

    __shared__ float sbox[2][NANCH][4];
    __shared__ ull   skey[2][NANCH];
    __shared__ int   topidx[2][TOPK];
    __shared__ float topsc [2][TOPK];
    __shared__ float kbox[2][TOPK][4];
    __shared__ int   keepf[2][TOPK];
    __shared__ int   woff[4];

    const float* preds[4] = {pred0, pred1, pred2, pred3};

    for (int a = tid; a < 2*NANCH; a += 384) {
        int b = a / NANCH, i = a - b*NANCH;
        int li, lv, H, stride;
        if      (i < 256) { li = i;       lv = 0; H = 16; stride = 32;  }
        else if (i < 320) { li = i - 256; lv = 1; H = 8;  stride = 64;  }
        else if (i < 336) { li = i - 320; lv = 2; H = 4;  stride = 128; }
        else              { li = i - 336; lv = 3; H = 2;  stride = 256; }
        int hw = H * H;
        const float* base = preds[lv] + b * 6 * hw;
        float v0 = base[li];
        float v1 = base[hw   + li];
        float v2 = base[2*hw + li];
        float v3 = base[3*hw + li];
        float v4 = base[4*hw + li];
        int y = li / H, x = li % H;
        float cx = (v0 + (float)x) * (float)stride;
        float cy = (v1 + (float)y) * (float)stride;
        float w  = expf(v2) * (float)stride;
        float h  = expf(v3) * (float)stride;
        sbox[b][i][0] = cx - w * 0.5f;
        sbox[b][i][1] = cy - h * 0.5f;
        sbox[b][i][2] = cx + w * 0.5f;
        sbox[b][i][3] = cy + h * 0.5f;
        float sc   = 1.f / (1.f + expf(-v4));
        float sval = (sc > 0.5f) ? sc : 0.f;
        skey[b][i] = ((ull)__float_as_uint(sval) << 32)
                   | (ull)(0xFFFFFFFFu - (unsigned)i);
    }
    __syncthreads();

    // warp 0 -> batch 0, warp 1 -> batch 1: 64 rounds, shfl reductions
    if (wid < 2) {
        int b = wid;
        for (int k = 0; k < TOPK; k++) {
            ull m = 0ULL;
            for (int i = lane; i < NANCH; i += 32) {
                ull v = skey[b][i]; if (v > m) m = v;
            }
            #pragma unroll
            for (int o = 16; o > 0; o >>= 1) {
                ull v = __shfl_down_sync(0xFFFFFFFFu, m, o);
                if (v > m) m = v;
            }
            m = __shfl_sync(0xFFFFFFFFu, m, 0);
            if (lane == 0) {
                int idx = (int)(0xFFFFFFFFu - (unsigned)(m & 0xFFFFFFFFu));
                topidx[b][k] = idx;
                topsc [b][k] = __uint_as_float((unsigned)(m >> 32));
                skey[b][idx] = 0ULL;
            }
            __syncwarp();
        }
    }
    __syncthreads();

    if (tid < 128) {
        int b = tid >> 6, j = tid & 63;
        int idx = topidx[b][j];
        for (int q = 0; q < 4; q++) kbox[b][j][q] = sbox[b][idx][q];
        keepf[b][j] = (topsc[b][j] > 0.5f) ? 1 : 0;
    }
    __syncthreads();

    for (int i = 0; i < TOPK; i++) {
        if (tid < 128) {
            int b = tid >> 6, j = tid & 63;
            if (j > i && keepf[b][j] && keepf[b][i]) {
                float ax0=kbox[b][i][0], ay0=kbox[b][i][1], ax1=kbox[b][i][2], ay1=kbox[b][i][3];
                float bx0=kbox[b][j][0], by0=kbox[b][j][1], bx1=kbox[b][j][2], by1=kbox[b][j][3];
                float aa = fmaxf(ax1-ax0,0.f)*fmaxf(ay1-ay0,0.f);
                float ab = fmaxf(bx1-bx0,0.f)*fmaxf(by1-by0,0.f);
                float ix0 = fmaxf(ax0,bx0), iy0 = fmaxf(ay0,by0);
                float ix1 = fminf(ax1,bx1), iy1 = fminf(ay1,by1);
                float inter = fmaxf(ix1-ix0,0.f)*fmaxf(iy1-iy0,0.f);
                float uni = aa + ab - inter;
                float iou = inter / fmaxf(uni, 1e-9f);
                if (iou > 0.5f) keepf[b][j] = 0;
            }
        }
        __syncthreads();
    }

    if (tid < 128) {
        int b = tid >> 6, j = tid & 63;
        int r = tid;
        int kp = keepf[b][j];
        out[OFF_SCORES + r] = kp ? topsc[b][j] : 0.f;
        for (int q = 0; q < 4; q++) out[OFF_BOXES + r*4 + q] = kbox[b][j][q];
        out[OFF_LABELS + r] = 0.f;
        out[OFF_KEEP   + r] = kp ? 1.f : 0.f;
        g_keep[r] = kp;
        for (int q = 0; q < 4; q++) {
            g_box[r][q] = kbox[b][j][q];
            float c = fminf(fmaxf(kbox[b][j][q], 0.f), 511.f);
            g_bint[r][q] = (int)c;
        }
    }
    __syncthreads();

    // compaction of kept rois (tids 0..127 = warps 0..3)
    if (tid < 128) {
        int kp = keepf[tid>>6][tid&63];
        unsigned ball = __ballot_sync(0xFFFFFFFFu, kp);
        if (lane == 0) woff[wid] = __popc(ball);
    }
    __syncthreads();
    if (tid == 0) {
        int s = 0;
        for (int w = 0; w < 4; w++) { int t = woff[w]; woff[w] = s; s += t; }
        g_nitems = 7 * s;
    }
    __syncthreads();
    if (tid < 128) {
        int kp = keepf[tid>>6][tid&63];
        unsigned ball = __ballot_sync(0xFFFFFFFFu, kp);
        int pre = __popc(ball & ((1u << lane) - 1u));
        if (kp) g_list[woff[wid] + pre] = tid;
    }
}

// =======================================================================
// K2: ROI-align from channel-last features: one LDG.128 = 4 channels/tap.
// grid (4 levels, 128 rois), 256 threads. Bilinear expression per channel
// identical to previous rounds -> g_roi bit-identical.
// =======================================================================
__global__ void k2_sample()
{
    int l = blockIdx.x;
    int r = blockIdx.y;
    if (!g_keep[r]) return;
    int b = r >> 6;
    int dim = 128 >> l;
    const float* ft = (l==0) ? g_ft0 : (l==1) ? g_ft1 : (l==2) ? g_ft2 : g_ft3;
    ft += (size_t)b * dim * dim * 64;

    float bx0 = g_box[r][0]*0.25f, by0 = g_box[r][1]*0.25f;
    float bx1 = g_box[r][2]*0.25f, by1 = g_box[r][3]*0.25f;
    float bw = (bx1 - bx0) / 28.f;
    float bh = (by1 - by0) / 28.f;

    for (int e = threadIdx.x; e < 16*900; e += 256) {
        int g4 = e / 900; int pe = e - g4*900;
        int py = pe / 30; int px = pe - py*30;
        int cl = g4 * 4;                       // channel-in-level 0..60
        float4 val = make_float4(0.f, 0.f, 0.f, 0.f);
        if (py >= 1 && py <= 28 && px >= 1 && px <= 28) {
            int gx = px - 1, gy = py - 1;
            float xx = bx0 + ((float)gx + 0.5f) * bw;
            float yy = by0 + ((float)gy + 0.5f) * bh;
            xx = fminf(fmaxf(xx, 0.f), 127.f);
            yy = fminf(fmaxf(yy, 0.f), 127.f);
            int x0 = (int)floorf(xx), y0 = (int)floorf(yy);
            int x1 = min(x0 + 1, 127), y1 = min(y0 + 1, 127);
            float fx = xx - (float)x0, fy = yy - (float)y0;
            int xA = x0 >> l, yA = y0 >> l, xB = x1 >> l, yB = y1 >> l;
            const float4* p00 = (const float4*)(ft + ((size_t)yA*dim + xA)*64 + cl);
            const float4* p01 = (const float4*)(ft + ((size_t)yA*dim + xB)*64 + cl);
            const float4* p10 = (const float4*)(ft + ((size_t)yB*dim + xA)*64 + cl);
            const float4* p11 = (const float4*)(ft + ((size_t)yB*dim + xB)*64 + cl);
            float4 v00 = *p00, v01 = *p01, v10 = *p10, v11 = *p11;
            val.x = v00.x*(1.f-fy)*(1.f-fx) + v01.x*(1.f-fy)*fx
                  + v10.x*fy*(1.f-fx)       + v11.x*fy*fx;
            val.y = v00.y*(1.f-fy)*(1.f-fx) + v01.y*(1.f-fy)*fx
                  + v10.y*fy*(1.f-fx)       + v11.y*fy*fx;
            val.z = v00.z*(1.f-fy)*(1.f-fx) + v01.z*(1.f-fy)*fx
                  + v10.z*fy*(1.f-fx)       + v11.z*fy*fx;
            val.w = v00.w*(1.f-fy)*(1.f-fx) + v01.w*(1.f-fy)*fx
                  + v10.w*fy*(1.f-fx)       + v11.w*fy*fx;
        }
        int c = l*64 + cl;
        g_roi[r][c+0][pe] = val.x;
        g_roi[r][c+1][pe] = val.y;
        g_roi[r][c+2][pe] = val.z;
        g_roi[r][c+3][pe] = val.w;
    }
}

// =======================================================================
// K3: conv1(3x3,256->128)+SiLU fused with conv2(1x1,128->1) -> logits.
// Single-barrier pipeline: CP_WAIT -> sync -> PREFETCH(next) -> compute ->
// COMMITIN(next). 64 iters, ONE __syncthreads each. 224 thr = 8 ty x 28 tx.
// Accumulation order per (oc,px) unchanged -> conv1 accs bit-identical.
// =======================================================================
__global__ void __launch_bounds__(224, 2)
k3_conv(const float* __restrict__ b1, const float* __restrict__ w2,
        const float* __restrict__ b2)
{
    int item = blockIdx.x;
    if (item >= g_nitems) return;
    int kidx = item / 7, rt = item - kidx*7;
    int r = g_list[kidx];

    int tid = threadIdx.x;            // 0..223
    int tx = tid % 28, ty = tid / 28; // tx: col, ty: oc group (16 oc)

    __shared__ __align__(16) float w_s[2][4608];   // [buf][(c*9+tap)*128+oc]
    __shared__ __align__(16) float in_s[2][4][180];// [buf][c][row*30+col]
    __shared__ float redbuf[8][112];

    // input prefetch: 720 elems/stage; slots e = tid + 224*j, j=0..3
    int en = (tid < 48) ? 4 : 3;      // 224*3=672, +48 = 720
    int ec[4], er[4];
    #pragma unroll
    for (int j = 0; j < 4; j++) {
        int e = tid + 224*j;
        if (e < 720) { ec[j] = e / 180; er[j] = e - ec[j]*180; }
        else         { ec[j] = 0;       er[j] = 0; }
    }
    const float* roi_base = &g_roi[r][0][0];
    int rowoff = rt * 120;            // (rt*4)*30

    uint32_t wdst[2] = { s2u(&w_s[0][0]), s2u(&w_s[1][0]) };
    float pin[4];

    // per-stage weight block: 4 ci * 9 taps * 128 oc = 4608 floats
    #define PREFETCH(s)                                                       \
    {                                                                         \
        const float* wsrc = g_w1t + (size_t)(s)*4608;                         \
        uint32_t wd = wdst[(s) & 1];                                          \
        for (int i = tid; i < 1152; i += 224)                                 \
            cpasync16(wd + i*16, wsrc + i*4);                                 \
        CP_COMMIT();                                                          \
        _Pragma("unroll")                                                     \
        for (int j = 0; j < 4; j++)                                           \
            if (j < en)                                                       \
                pin[j] = roi_base[(size_t)(4*(s) + ec[j])*900 + rowoff + er[j]];\
    }
    #define COMMITIN(s)                                                       \
    {                                                                         \
        _Pragma("unroll")                                                     \
        for (int j = 0; j < 4; j++)                                           \
            if (j < en)                                                       \
                in_s[(s)&1][ec[j]][er[j]] = pin[j];                           \
    }

    ull acc[8][4];                    // 8 oc-pairs x 4 px (rows)
    ull z = pack2(0.f);
    #pragma unroll
    for (int j = 0; j < 8; j++)
        #pragma unroll
        for (int p = 0; p < 4; p++) acc[j][p] = z;

    int oc0 = ty * 16;

    // prologue: stage 0 weights + inputs (one-time LDG stall on pin)
    PREFETCH(0);
    COMMITIN(0);

    for (int it = 0; it < 64; it++) {
        int cur = it & 1;
        CP_WAIT0();                    // weights(it) landed (committed last iter)
        __syncthreads();               // in_s[cur] visible; all readers of the
                                       // buffers we are about to overwrite are done
        if (it + 1 < 64) PREFETCH(it + 1);   // cp.async w(it+1) + LDG pin(it+1)

        const float* wbuf = &w_s[cur][0];
        #pragma unroll
        for (int c = 0; c < 4; c++) {
            #pragma unroll
            for (int ky = 0; ky < 3; ky++) {
                #pragma unroll
                for (int kx = 0; kx < 3; kx++) {
                    const ulonglong2* wp =
                        (const ulonglong2*)(wbuf + (c*9 + ky*3 + kx)*128 + oc0);
                    ulonglong2 wq0 = wp[0], wq1 = wp[1];   // oc pairs 0..3
                    ulonglong2 wq2 = wp[2], wq3 = wp[3];   // oc pairs 4..7
                    const float* ib = &in_s[cur][c][ky*30 + kx + tx];
                    #pragma unroll
                    for (int p = 0; p < 4; p++) {
                        ull bb = pack2(ib[p*30]);
                        fma2(acc[0][p], wq0.x, bb);
                        fma2(acc[1][p], wq0.y, bb);
                        fma2(acc[2][p], wq1.x, bb);
                        fma2(acc[3][p], wq1.y, bb);
                        fma2(acc[4][p], wq2.x, bb);
                        fma2(acc[5][p], wq2.y, bb);
                        fma2(acc[6][p], wq3.x, bb);
                        fma2(acc[7][p], wq3.y, bb);
                    }
                }
            }
        }
        if (it + 1 < 64) COMMITIN(it + 1);   // STS next buffer (no barrier here)
    }
    #undef PREFETCH
    #undef COMMITIN

    // SiLU + 1x1 conv partials (oc ascending within thread)
    float lp[4];
    #pragma unroll
    for (int p = 0; p < 4; p++) lp[p] = 0.f;
    #pragma unroll
    for (int j = 0; j < 8; j++) {
        int oca = oc0 + 2*j, ocb = oc0 + 2*j + 1;
        float ba = b1[oca], bb_ = b1[ocb];
        float wa = w2[oca], wb = w2[ocb];
        #pragma unroll
        for (int p = 0; p < 4; p++) {
            float2 v = unpack2(acc[j][p]);
            float ha = v.x + ba;
            float hb = v.y + bb_;
            lp[p] += wa * (ha / (1.f + expf(-ha)));
            lp[p] += wb * (hb / (1.f + expf(-hb)));
        }
    }
    #pragma unroll
    for (int p = 0; p < 4; p++) redbuf[ty][p*28 + tx] = lp[p];
    __syncthreads();
    if (tid < 112) {
        float s = b2[0];
        #pragma unroll
        for (int t = 0; t < 8; t++) s += redbuf[t][tid];
        int row = rt*4 + tid / 28, col = tid % 28;
        g_logit[r][row*28 + col] = s;   // sign(logit) == (sigmoid > 0.5)
    }
}

// =======================================================================
// K4: paste -> binary masks (float 0/1). grid (512 rows, 128 rois), 128 thr
// =======================================================================
__global__ void k4_paste(float* __restrict__ out)
{
    int r = blockIdx.y;
    int y = blockIdx.x;
    int tid = threadIdx.x;
    float4* dst = (float4*)(out + OFF_MASKS + (size_t)r*262144 + (size_t)y*512);

    __shared__ float brow[28];
    float4 v = make_float4(0.f, 0.f, 0.f, 0.f);
    int kp = g_keep[r];
    if (kp) {
        int x0 = g_bint[r][0], y0 = g_bint[r][1];
        int x1 = g_bint[r][2], y1 = g_bint[r][3];
        if (y >= y0 && y <= y1) {
            int h = y1 - y0 + 1, w = x1 - x0 + 1;
            int iy = min((y - y0) * 28 / h, 27);
            if (tid < 28) brow[tid] = (g_logit[r][iy*28 + tid] > 0.f) ? 1.f : 0.f;
            __syncthreads();
            float* vv = (float*)&v;
            #pragma unroll
            for (int q = 0; q < 4; q++) {
                int x = tid * 4 + q;
                if (x >= x0 && x <= x1) {
                    int ix = min((x - x0) * 28 / w, 27);
                    vv[q] = brow[ix];
                }
            }
        }
    }
    dst[tid] = v;
}

// =======================================================================
extern "C" void kernel_launch(void* const* d_in, const int* in_sizes, int n_in,
                              void* d_out, int out_size)
{
    const float* pred0 = (const float*)d_in[0];
    const float* pred1 = (const float*)d_in[1];
    const float* pred2 = (const float*)d_in[2];
    const float* pred3 = (const float*)d_in[3];
    const float* feat0 = (const float*)d_in[4];
    const float* feat1 = (const float*)d_in[5];
    const float* feat2 = (const float*)d_in[6];
    const float* feat3 = (const float*)d_in[7];
    const float* w1    = (const float*)d_in[8];
    const float* b1    = (const float*)d_in[9];
    const float* w2    = (const float*)d_in[10];
    const float* b2    = (const float*)d_in[11];
    float* out = (float*)d_out;
    (void)in_sizes; (void)n_in; (void)out_size;

    float* ft0; cudaGetSymbolAddress((void**)&ft0, g_ft0);
    float* ft1; cudaGetSymbolAddress((void**)&ft1, g_ft1);
    float* ft2; cudaGetSymbolAddress((void**)&ft2, g_ft2);
    float* ft3; cudaGetSymbolAddress((void**)&ft3, g_ft3);

    k0_wt <<<1152, 256>>>(w1);
    k0_ft <<<(2*64*128*128 + 255)/256, 256>>>(feat0, ft0, 128);
    k0_ft <<<(2*64* 64* 64 + 255)/256, 256>>>(feat1, ft1,  64);
    k0_ft <<<(2*64* 32* 32 + 255)/256, 256>>>(feat2, ft2,  32);
    k0_ft <<<(2*64* 16* 16 + 255)/256, 256>>>(feat3, ft3,  16);
    k1_detect<<<1, 384>>>(pred0, pred1, pred2, pred3, out);
    k2_sample<<<dim3(4, NROI), 256>>>();
    k3_conv  <<<7 * NROI, 224>>>(b1, w2, b2);
    k4_paste <<<dim3(512, NROI), 128>>>(out);
}

// round 13
// speedup vs baseline: 1.0302x; 1.0061x over previous
#include <cuda_runtime.h>
#include <math.h>
#include <stdint.h>

#define TOPK   64
#define NANCH  340
#define MS     28
#define NROI   128          // B(2) * TOPK(64)

typedef unsigned long long ull;

// ---------------- device scratch (no allocation allowed) ----------------
__device__ float g_box [NROI][4];
__device__ int   g_bint[NROI][4];
__device__ int   g_keep[NROI];
__device__ int   g_list[NROI];     // compacted kept roi ids
__device__ int   g_nitems;         // 7 * nkept
__device__ int   g_ctr;            // work-stealing counter for k3
__device__ float g_logit[NROI][MS*MS];
__device__ float g_roi[NROI][256][900];       // padded 30x30 per channel
__device__ float g_w1t[256*9*128];            // [(ci*9+tap)*128 + oc]
// channel-last transposed features: [b][y][x][c], c fastest (64 per level)
__device__ __align__(16) float g_ft0[2*128*128*64];
__device__ __align__(16) float g_ft1[2* 64* 64*64];
__device__ __align__(16) float g_ft2[2* 32* 32*64];
__device__ __align__(16) float g_ft3[2* 16* 16*64];

// out layout (fp32): scores[128] | boxes[512] | labels[128] | masks[2*64*512*512] | keep[128]
#define OFF_SCORES 0
#define OFF_BOXES  128
#define OFF_LABELS 640
#define OFF_MASKS  768
#define OFF_KEEP   33555200

// ---------------- packed fp32x2 helpers (Blackwell FFMA2) ----------------
__device__ __forceinline__ ull pack2(float x) {
    ull r; asm("mov.b64 %0, {%1, %1};" : "=l"(r) : "f"(x)); return r;
}
__device__ __forceinline__ void fma2(ull& d, ull a, ull b) {
    asm("fma.rn.f32x2 %0, %1, %2, %0;" : "+l"(d) : "l"(a), "l"(b));
}
__device__ __forceinline__ float2 unpack2(ull v) {
    float2 f; asm("mov.b64 {%0, %1}, %2;" : "=f"(f.x), "=f"(f.y) : "l"(v)); return f;
}
__device__ __forceinline__ uint32_t s2u(const void* p) {
    return (uint32_t)__cvta_generic_to_shared(p);
}
__device__ __forceinline__ void cpasync16(uint32_t smem, const void* g) {
    asm volatile("cp.async.ca.shared.global [%0], [%1], 16;" :: "r"(smem), "l"(g));
}
#define CP_COMMIT()  asm volatile("cp.async.commit_group;" ::: "memory")
#define CP_WAIT0()   asm volatile("cp.async.wait_group 0;" ::: "memory")

// =======================================================================
// K0a: transpose conv1 weights -> g_w1t[(ci*9+tap)*128 + oc]
// =======================================================================
__global__ void k0_wt(const float* __restrict__ w1)
{
    int idx = blockIdx.x * 256 + threadIdx.x;
    if (idx < 256*9*128) {
        int oc = idx & 127;
        int ct = idx >> 7;          // ci*9+tap
        int ci = ct / 9, tap = ct - ci*9;
        g_w1t[idx] = w1[(size_t)oc*2304 + ci*9 + tap];
    }
}

// =======================================================================
// K0b: transpose features [b][c][y][x] -> [b][y][x][c] (c fastest)
// =======================================================================
__global__ void k0_ft(const float* __restrict__ src, float* __restrict__ dst,
                      int dim)
{
    int idx = blockIdx.x * 256 + threadIdx.x;
    int total = 2 * 64 * dim * dim;
    if (idx >= total) return;
    int x = idx % dim; int t = idx / dim;
    int y = t % dim;   t /= dim;
    int c = t % 64;    int b = t / 64;
    dst[(size_t)(((b*dim) + y)*dim + x)*64 + c] = src[idx];
}

// =======================================================================
// K1: decode + warp-shuffle top-k + NMS + outputs + compaction (1 block)
// =======================================================================
__global__ void k1_detect(const float* __restrict__ pred0,
                          const float* __restrict__ pred1,
                          const float* __restrict__ pred2,
                          const float* __restrict__ pred3,
                          float* __restrict__ out)
{
    int tid  = threadIdx.x;           // 384
    int wid  = tid >> 5, lane = tid & 31;

    __shared__ float sbox[2][NANCH][4];
    __shared__ ull   skey[2][NANCH];
    __shared__ int   topidx[2][TOPK];
    __shared__ float topsc [2][TOPK];
    __shared__ float kbox[2][TOPK][4];
    __shared__ int   keepf[2][TOPK];
    __shared__ int   woff[4];

    const float* preds[4] = {pred0, pred1, pred2, pred3};

    for (int a = tid; a < 2*NANCH; a += 384) {
        int b = a / NANCH, i = a - b*NANCH;
        int li, lv, H, stride;
        if      (i < 256) { li = i;       lv = 0; H = 16; stride = 32;  }
        else if (i < 320) { li = i - 256; lv = 1; H = 8;  stride = 64;  }
        else if (i < 336) { li = i - 320; lv = 2; H = 4;  stride = 128; }
        else              { li = i - 336; lv = 3; H = 2;  stride = 256; }
        int hw = H * H;
        const float* base = preds[lv] + b * 6 * hw;
        float v0 = base[li];
        float v1 = base[hw   + li];
        float v2 = base[2*hw + li];
        float v3 = base[3*hw + li];
        float v4 = base[4*hw + li];
        int y = li / H, x = li % H;
        float cx = (v0 + (float)x) * (float)stride;
        float cy = (v1 + (float)y) * (float)stride;
        float w  = expf(v2) * (float)stride;
        float h  = expf(v3) * (float)stride;
        sbox[b][i][0] = cx - w * 0.5f;
        sbox[b][i][1] = cy - h * 0.5f;
        sbox[b][i][2] = cx + w * 0.5f;
        sbox[b][i][3] = cy + h * 0.5f;
        float sc   = 1.f / (1.f + expf(-v4));
        float sval = (sc > 0.5f) ? sc : 0.f;
        skey[b][i] = ((ull)__float_as_uint(sval) << 32)
                   | (ull)(0xFFFFFFFFu - (unsigned)i);
    }
    __syncthreads();

    // warp 0 -> batch 0, warp 1 -> batch 1: 64 rounds, shfl reductions
    if (wid < 2) {
        int b = wid;
        for (int k = 0; k < TOPK; k++) {
            ull m = 0ULL;
            for (int i = lane; i < NANCH; i += 32) {
                ull v = skey[b][i]; if (v > m) m = v;
            }
            #pragma unroll
            for (int o = 16; o > 0; o >>= 1) {
                ull v = __shfl_down_sync(0xFFFFFFFFu, m, o);
                if (v > m) m = v;
            }
            m = __shfl_sync(0xFFFFFFFFu, m, 0);
            if (lane == 0) {
                int idx = (int)(0xFFFFFFFFu - (unsigned)(m & 0xFFFFFFFFu));
                topidx[b][k] = idx;
                topsc [b][k] = __uint_as_float((unsigned)(m >> 32));
                skey[b][idx] = 0ULL;
            }
            __syncwarp();
        }
    }
    __syncthreads();

    if (tid < 128) {
        int b = tid >> 6, j = tid & 63;
        int idx = topidx[b][j];
        for (int q = 0; q < 4; q++) kbox[b][j][q] = sbox[b][idx][q];
        keepf[b][j] = (topsc[b][j] > 0.5f) ? 1 : 0;
    }
    __syncthreads();

    for (int i = 0; i < TOPK; i++) {
        if (tid < 128) {
            int b = tid >> 6, j = tid & 63;
            if (j > i && keepf[b][j] && keepf[b][i]) {
                float ax0=kbox[b][i][0], ay0=kbox[b][i][1], ax1=kbox[b][i][2], ay1=kbox[b][i][3];
                float bx0=kbox[b][j][0], by0=kbox[b][j][1], bx1=kbox[b][j][2], by1=kbox[b][j][3];
                float aa = fmaxf(ax1-ax0,0.f)*fmaxf(ay1-ay0,0.f);
                float ab = fmaxf(bx1-bx0,0.f)*fmaxf(by1-by0,0.f);
                float ix0 = fmaxf(ax0,bx0), iy0 = fmaxf(ay0,by0);
                float ix1 = fminf(ax1,bx1), iy1 = fminf(ay1,by1);
                float inter = fmaxf(ix1-ix0,0.f)*fmaxf(iy1-iy0,0.f);
                float uni = aa + ab - inter;
                float iou = inter / fmaxf(uni, 1e-9f);
                if (iou > 0.5f) keepf[b][j] = 0;
            }
        }
        __syncthreads();
    }

    if (tid < 128) {
        int b = tid >> 6, j = tid & 63;
        int r = tid;
        int kp = keepf[b][j];
        out[OFF_SCORES + r] = kp ? topsc[b][j] : 0.f;
        for (int q = 0; q < 4; q++) out[OFF_BOXES + r*4 + q] = kbox[b][j][q];
        out[OFF_LABELS + r] = 0.f;
        out[OFF_KEEP   + r] = kp ? 1.f : 0.f;
        g_keep[r] = kp;
        for (int q = 0; q < 4; q++) {
            g_box[r][q] = kbox[b][j][q];
            float c = fminf(fmaxf(kbox[b][j][q], 0.f), 511.f);
            g_bint[r][q] = (int)c;
        }
    }
    __syncthreads();

    // compaction of kept rois (tids 0..127 = warps 0..3)
    if (tid < 128) {
        int kp = keepf[tid>>6][tid&63];
        unsigned ball = __ballot_sync(0xFFFFFFFFu, kp);
        if (lane == 0) woff[wid] = __popc(ball);
    }
    __syncthreads();
    if (tid == 0) {
        int s = 0;
        for (int w = 0; w < 4; w++) { int t = woff[w]; woff[w] = s; s += t; }
        g_nitems = 7 * s;
        g_ctr = 0;                      // reset k3 work-stealing counter
    }
    __syncthreads();
    if (tid < 128) {
        int kp = keepf[tid>>6][tid&63];
        unsigned ball = __ballot_sync(0xFFFFFFFFu, kp);
        int pre = __popc(ball & ((1u << lane) - 1u));
        if (kp) g_list[woff[wid] + pre] = tid;
    }
}

// =======================================================================
// K2: ROI-align from channel-last features: one LDG.128 = 4 channels/tap.
// =======================================================================
__global__ void k2_sample()
{
    int l = blockIdx.x;
    int r = blockIdx.y;
    if (!g_keep[r]) return;
    int b = r >> 6;
    int dim = 128 >> l;
    const float* ft = (l==0) ? g_ft0 : (l==1) ? g_ft1 : (l==2) ? g_ft2 : g_ft3;
    ft += (size_t)b * dim * dim * 64;

    float bx0 = g_box[r][0]*0.25f, by0 = g_box[r][1]*0.25f;
    float bx1 = g_box[r][2]*0.25f, by1 = g_box[r][3]*0.25f;
    float bw = (bx1 - bx0) / 28.f;
    float bh = (by1 - by0) / 28.f;

    for (int e = threadIdx.x; e < 16*900; e += 256) {
        int g4 = e / 900; int pe = e - g4*900;
        int py = pe / 30; int px = pe - py*30;
        int cl = g4 * 4;                       // channel-in-level 0..60
        float4 val = make_float4(0.f, 0.f, 0.f, 0.f);
        if (py >= 1 && py <= 28 && px >= 1 && px <= 28) {
            int gx = px - 1, gy = py - 1;
            float xx = bx0 + ((float)gx + 0.5f) * bw;
            float yy = by0 + ((float)gy + 0.5f) * bh;
            xx = fminf(fmaxf(xx, 0.f), 127.f);
            yy = fminf(fmaxf(yy, 0.f), 127.f);
            int x0 = (int)floorf(xx), y0 = (int)floorf(yy);
            int x1 = min(x0 + 1, 127), y1 = min(y0 + 1, 127);
            float fx = xx - (float)x0, fy = yy - (float)y0;
            int xA = x0 >> l, yA = y0 >> l, xB = x1 >> l, yB = y1 >> l;
            const float4* p00 = (const float4*)(ft + ((size_t)yA*dim + xA)*64 + cl);
            const float4* p01 = (const float4*)(ft + ((size_t)yA*dim + xB)*64 + cl);
            const float4* p10 = (const float4*)(ft + ((size_t)yB*dim + xA)*64 + cl);
            const float4* p11 = (const float4*)(ft + ((size_t)yB*dim + xB)*64 + cl);
            float4 v00 = *p00, v01 = *p01, v10 = *p10, v11 = *p11;
            val.x = v00.x*(1.f-fy)*(1.f-fx) + v01.x*(1.f-fy)*fx
                  + v10.x*fy*(1.f-fx)       + v11.x*fy*fx;
            val.y = v00.y*(1.f-fy)*(1.f-fx) + v01.y*(1.f-fy)*fx
                  + v10.y*fy*(1.f-fx)       + v11.y*fy*fx;
            val.z = v00.z*(1.f-fy)*(1.f-fx) + v01.z*(1.f-fy)*fx
                  + v10.z*fy*(1.f-fx)       + v11.z*fy*fx;
            val.w = v00.w*(1.f-fy)*(1.f-fx) + v01.w*(1.f-fy)*fx
                  + v10.w*fy*(1.f-fx)       + v11.w*fy*fx;
        }
        int c = l*64 + cl;
        g_roi[r][c+0][pe] = val.x;
        g_roi[r][c+1][pe] = val.y;
        g_roi[r][c+2][pe] = val.z;
        g_roi[r][c+3][pe] = val.w;
    }
}

// =======================================================================
// K3: conv1(3x3,256->128)+SiLU fused with conv2(1x1,128->1) -> logits.
// PERSISTENT blocks (296 = 2/SM x 148): each block loops items claimed via
// atomicAdd(g_ctr) -> zero wave quantization. Item body identical to R11:
// single-barrier cp.async pipeline, 64 stages of 4 input channels.
// Accumulation order per (oc,px) unchanged -> bit-identical logits.
// =======================================================================
__global__ void __launch_bounds__(224, 2)
k3_conv(const float* __restrict__ b1, const float* __restrict__ w2,
        const float* __restrict__ b2)
{
    int tid = threadIdx.x;            // 0..223
    int tx = tid % 28, ty = tid / 28; // tx: col, ty: oc group (16 oc)

    __shared__ __align__(16) float w_s[2][4608];   // [buf][(c*9+tap)*128+oc]
    __shared__ __align__(16) float in_s[2][4][180];// [buf][c][row*30+col]
    __shared__ float redbuf[8][112];
    __shared__ int   sh_item;

    // input prefetch descriptors (item-invariant): 720 elems/stage
    int en = (tid < 48) ? 4 : 3;      // 224*3=672, +48 = 720
    int ec[4], er[4];
    #pragma unroll
    for (int j = 0; j < 4; j++) {
        int e = tid + 224*j;
        if (e < 720) { ec[j] = e / 180; er[j] = e - ec[j]*180; }
        else         { ec[j] = 0;       er[j] = 0; }
    }
    uint32_t wdst[2] = { s2u(&w_s[0][0]), s2u(&w_s[1][0]) };
    int oc0 = ty * 16;

    while (true) {
        if (tid == 0) sh_item = atomicAdd(&g_ctr, 1);
        __syncthreads();                    // broadcast item; also fences
                                            // previous item's redbuf reads
        int item = sh_item;
        if (item >= g_nitems) break;

        int kidx = item / 7, rt = item - kidx*7;
        int r = g_list[kidx];
        const float* roi_base = &g_roi[r][0][0];
        int rowoff = rt * 120;              // (rt*4)*30
        float pin[4];

        // per-stage weight block: 4 ci * 9 taps * 128 oc = 4608 floats
        #define PREFETCH(s)                                                   \
        {                                                                     \
            const float* wsrc = g_w1t + (size_t)(s)*4608;                     \
            uint32_t wd = wdst[(s) & 1];                                      \
            for (int i = tid; i < 1152; i += 224)                             \
                cpasync16(wd + i*16, wsrc + i*4);                             \
            CP_COMMIT();                                                      \
            _Pragma("unroll")                                                 \
            for (int j = 0; j < 4; j++)                                       \
                if (j < en)                                                   \
                    pin[j] = roi_base[(size_t)(4*(s) + ec[j])*900 + rowoff + er[j]];\
        }
        #define COMMITIN(s)                                                   \
        {                                                                     \
            _Pragma("unroll")                                                 \
            for (int j = 0; j < 4; j++)                                       \
                if (j < en)                                                   \
                    in_s[(s)&1][ec[j]][er[j]] = pin[j];                       \
        }

        ull acc[8][4];                      // 8 oc-pairs x 4 px (rows)
        ull z = pack2(0.f);
        #pragma unroll
        for (int j = 0; j < 8; j++)
            #pragma unroll
            for (int p = 0; p < 4; p++) acc[j][p] = z;

        // prologue: stage 0 weights + inputs
        PREFETCH(0);
        COMMITIN(0);

        for (int it = 0; it < 64; it++) {
            int cur = it & 1;
            CP_WAIT0();                     // weights(it) landed
            __syncthreads();                // in_s[cur] visible; overwrite-safe
            if (it + 1 < 64) PREFETCH(it + 1);

            const float* wbuf = &w_s[cur][0];
            #pragma unroll
            for (int c = 0; c < 4; c++) {
                #pragma unroll
                for (int ky = 0; ky < 3; ky++) {
                    #pragma unroll
                    for (int kx = 0; kx < 3; kx++) {
                        const ulonglong2* wp =
                            (const ulonglong2*)(wbuf + (c*9 + ky*3 + kx)*128 + oc0);
                        ulonglong2 wq0 = wp[0], wq1 = wp[1];
                        ulonglong2 wq2 = wp[2], wq3 = wp[3];
                        const float* ib = &in_s[cur][c][ky*30 + kx + tx];
                        #pragma unroll
                        for (int p = 0; p < 4; p++) {
                            ull bb = pack2(ib[p*30]);
                            fma2(acc[0][p], wq0.x, bb);
                            fma2(acc[1][p], wq0.y, bb);
                            fma2(acc[2][p], wq1.x, bb);
                            fma2(acc[3][p], wq1.y, bb);
                            fma2(acc[4][p], wq2.x, bb);
                            fma2(acc[5][p], wq2.y, bb);
                            fma2(acc[6][p], wq3.x, bb);
                            fma2(acc[7][p], wq3.y, bb);
                        }
                    }
                }
            }
            if (it + 1 < 64) COMMITIN(it + 1);
        }
        #undef PREFETCH
        #undef COMMITIN

        // SiLU + 1x1 conv partials (oc ascending within thread)
        float lp[4];
        #pragma unroll
        for (int p = 0; p < 4; p++) lp[p] = 0.f;
        #pragma unroll
        for (int j = 0; j < 8; j++) {
            int oca = oc0 + 2*j, ocb = oc0 + 2*j + 1;
            float ba = b1[oca], bb_ = b1[ocb];
            float wa = w2[oca], wb = w2[ocb];
            #pragma unroll
            for (int p = 0; p < 4; p++) {
                float2 v = unpack2(acc[j][p]);
                float ha = v.x + ba;
                float hb = v.y + bb_;
                lp[p] += wa * (ha / (1.f + expf(-ha)));
                lp[p] += wb * (hb / (1.f + expf(-hb)));
            }
        }
        #pragma unroll
        for (int p = 0; p < 4; p++) redbuf[ty][p*28 + tx] = lp[p];
        __syncthreads();
        if (tid < 112) {
            float s = b2[0];
            #pragma unroll
            for (int t = 0; t < 8; t++) s += redbuf[t][tid];
            int row = rt*4 + tid / 28, col = tid % 28;
            g_logit[r][row*28 + col] = s;   // sign(logit) == (sigmoid > 0.5)
        }
    }
}

// =======================================================================
// K4: paste -> binary masks (float 0/1). grid (512 rows, 128 rois), 128 thr
// =======================================================================
__global__ void k4_paste(float* __restrict__ out)
{
    int r = blockIdx.y;
    int y = blockIdx.x;
    int tid = threadIdx.x;
    float4* dst = (float4*)(out + OFF_MASKS + (size_t)r*262144 + (size_t)y*512);

    __shared__ float brow[28];
    float4 v = make_float4(0.f, 0.f, 0.f, 0.f);
    int kp = g_keep[r];
    if (kp) {
        int x0 = g_bint[r][0], y0 = g_bint[r][1];
        int x1 = g_bint[r][2], y1 = g_bint[r][3];
        if (y >= y0 && y <= y1) {
            int h = y1 - y0 + 1, w = x1 - x0 + 1;
            int iy = min((y - y0) * 28 / h, 27);
            if (tid < 28) brow[tid] = (g_logit[r][iy*28 + tid] > 0.f) ? 1.f : 0.f;
            __syncthreads();
            float* vv = (float*)&v;
            #pragma unroll
            for (int q = 0; q < 4; q++) {
                int x = tid * 4 + q;
                if (x >= x0 && x <= x1) {
                    int ix = min((x - x0) * 28 / w, 27);
                    vv[q] = brow[ix];
                }
            }
        }
    }
    dst[tid] = v;
}

// =======================================================================
extern "C" void kernel_launch(void* const* d_in, const int* in_sizes, int n_in,
                              void* d_out, int out_size)
{
    const float* pred0 = (const float*)d_in[0];
    const float* pred1 = (const float*)d_in[1];
    const float* pred2 = (const float*)d_in[2];
    const float* pred3 = (const float*)d_in[3];
    const float* feat0 = (const float*)d_in[4];
    const float* feat1 = (const float*)d_in[5];
    const float* feat2 = (const float*)d_in[6];
    const float* feat3 = (const float*)d_in[7];
    const float* w1    = (const float*)d_in[8];
    const float* b1    = (const float*)d_in[9];
    const float* w2    = (const float*)d_in[10];
    const float* b2    = (const float*)d_in[11];
    float* out = (float*)d_out;
    (void)in_sizes; (void)n_in; (void)out_size;

    float* ft0; cudaGetSymbolAddress((void**)&ft0, g_ft0);
    float* ft1; cudaGetSymbolAddress((void**)&ft1, g_ft1);
    float* ft2; cudaGetSymbolAddress((void**)&ft2, g_ft2);
    float* ft3; cudaGetSymbolAddress((void**)&ft3, g_ft3);

    k0_wt <<<1152, 256>>>(w1);
    k0_ft <<<(2*64*128*128 + 255)/256, 256>>>(feat0, ft0, 128);
    k0_ft <<<(2*64* 64* 64 + 255)/256, 256>>>(feat1, ft1,  64);
    k0_ft <<<(2*64* 32* 32 + 255)/256, 256>>>(feat2, ft2,  32);
    k0_ft <<<(2*64* 16* 16 + 255)/256, 256>>>(feat3, ft3,  16);
    k1_detect<<<1, 384>>>(pred0, pred1, pred2, pred3, out);
    k2_sample<<<dim3(4, NROI), 256>>>();
    k3_conv  <<<296, 224>>>(b1, w2, b2);
    k4_paste <<<dim3(512, NROI), 128>>>(out);
}